// round 2
// baseline (speedup 1.0000x reference)
#include <cuda_runtime.h>
#include <cuda_bf16.h>
#include <math.h>

// ---------------- problem constants ----------------
#define BSZ     2
#define LEN     1024
#define DMODEL  1024
#define DIN     2048      // d_inner
#define NST     16        // n_state
#define DTR     64        // dt_rank
#define XPW     96        // dt_rank + 2*n_state
#define CHUNK   256
#define NC      (LEN / CHUNK)
#define MROWS   (BSZ * LEN)   // 2048

// ---------------- scratch (device globals; no allocation allowed) ----------------
__device__ __align__(16) float g_xr[(size_t)BSZ * LEN * 2 * DIN];   // in_proj output (xc | res)
__device__ __align__(16) float g_u [(size_t)BSZ * LEN * DIN];       // conv+silu output
__device__ __align__(16) float g_xp[(size_t)BSZ * LEN * XPW];       // x_proj output (dlt|B|C)
__device__ __align__(16) float g_dl[(size_t)BSZ * LEN * DIN];       // delta (softplus'd)
__device__ __align__(16) float g_y [(size_t)BSZ * LEN * DIN];       // gated scan output

// ---------------- generic SGEMM:  C[M,N] = A[M,K] @ B[N,K]^T (+bias) (+act) ----------------
// A row-major stride lda, B row-major stride ldb (K contiguous in both), C stride ldc.
// ACT: 0 = none, 1 = softplus
template <int ACT>
__global__ void __launch_bounds__(256)
sgemm_bt(const float* __restrict__ A, const float* __restrict__ B,
         const float* __restrict__ bias, float* __restrict__ C,
         int M, int N, int K, int lda, int ldb, int ldc)
{
    __shared__ float As[8][128];
    __shared__ float Bs[8][128];

    const int tid  = threadIdx.x;
    const int tx   = tid & 15;        // 0..15  (N micro)
    const int ty   = tid >> 4;        // 0..15  (M micro)
    const int brow = blockIdx.y * 128;
    const int bcol = blockIdx.x * 128;

    const int l_row = tid >> 1;             // 0..127
    const int l_col = (tid & 1) * 4;        // 0 or 4

    const float* Ab = A + (size_t)brow * lda;
    const float* Bb = B + (size_t)bcol * ldb;

    float acc[8][8];
#pragma unroll
    for (int i = 0; i < 8; i++)
#pragma unroll
        for (int j = 0; j < 8; j++) acc[i][j] = 0.f;

    for (int k0 = 0; k0 < K; k0 += 8) {
        // load A tile 128x8 (M rows guaranteed in-bounds: M multiple of 128)
        float4 av = *(const float4*)(Ab + (size_t)l_row * lda + k0 + l_col);
        As[l_col + 0][l_row] = av.x;
        As[l_col + 1][l_row] = av.y;
        As[l_col + 2][l_row] = av.z;
        As[l_col + 3][l_row] = av.w;
        // load B tile 128x8 with N guard
        float4 bv = make_float4(0.f, 0.f, 0.f, 0.f);
        if (bcol + l_row < N)
            bv = *(const float4*)(Bb + (size_t)l_row * ldb + k0 + l_col);
        Bs[l_col + 0][l_row] = bv.x;
        Bs[l_col + 1][l_row] = bv.y;
        Bs[l_col + 2][l_row] = bv.z;
        Bs[l_col + 3][l_row] = bv.w;
        __syncthreads();

#pragma unroll
        for (int kk = 0; kk < 8; kk++) {
            float ra[8], rb[8];
#pragma unroll
            for (int i = 0; i < 8; i++) ra[i] = As[kk][ty * 8 + i];
#pragma unroll
            for (int j = 0; j < 8; j++) rb[j] = Bs[kk][tx * 8 + j];
#pragma unroll
            for (int i = 0; i < 8; i++)
#pragma unroll
                for (int j = 0; j < 8; j++) acc[i][j] = fmaf(ra[i], rb[j], acc[i][j]);
        }
        __syncthreads();
    }

#pragma unroll
    for (int i = 0; i < 8; i++) {
        const int row = brow + ty * 8 + i;
#pragma unroll
        for (int j = 0; j < 8; j++) {
            const int col = bcol + tx * 8 + j;
            if (col < N) {
                float v = acc[i][j];
                if (bias) v += bias[col];
                if (ACT == 1) {           // softplus, matches jax.nn.softplus
                    v = (v > 20.f) ? v : log1pf(__expf(v));
                }
                C[(size_t)row * ldc + col] = v;
            }
        }
    }
}

// ---------------- depthwise causal conv1d (k=3) + SiLU ----------------
__global__ void conv_silu_kernel(const float* __restrict__ xr,
                                 const float* __restrict__ conv_w,
                                 const float* __restrict__ conv_b,
                                 float* __restrict__ u)
{
    const int idx = blockIdx.x * blockDim.x + threadIdx.x;   // over B*L*D
    if (idx >= BSZ * LEN * DIN) return;
    const int d = idx % DIN;
    const int l = (idx / DIN) % LEN;
    const int b = idx / (DIN * LEN);

    const float* xc = xr + (size_t)b * LEN * (2 * DIN);   // xc = first DIN cols of xr rows
    const float w0 = conv_w[d * 3 + 0];
    const float w1 = conv_w[d * 3 + 1];
    const float w2 = conv_w[d * 3 + 2];

    float acc = conv_b[d];
    if (l >= 2) acc = fmaf(w0, xc[(size_t)(l - 2) * (2 * DIN) + d], acc);
    if (l >= 1) acc = fmaf(w1, xc[(size_t)(l - 1) * (2 * DIN) + d], acc);
    acc = fmaf(w2, xc[(size_t)l * (2 * DIN) + d], acc);
    // silu
    u[idx] = acc / (1.f + __expf(-acc));
}

// ---------------- chunked selective scan + output gate ----------------
// grid: (D/256, NC, B), block 256. Each thread owns one d-channel for one chunk.
__global__ void __launch_bounds__(256)
scan_kernel(const float* __restrict__ xp, const float* __restrict__ delta,
            const float* __restrict__ u, const float* __restrict__ xr,
            const float* __restrict__ A_log, float* __restrict__ y)
{
    const int d = blockIdx.x * 256 + threadIdx.x;
    const int c = blockIdx.y;
    const int b = blockIdx.z;
    const int base_l = c * CHUNK;

    __shared__ float Bs[CHUNK][NST];
    __shared__ float Cs[CHUNK][NST];
    for (int i = threadIdx.x; i < CHUNK * NST; i += 256) {
        const int l = i / NST, n = i % NST;
        const float* row = xp + (size_t)(b * LEN + base_l + l) * XPW;
        Bs[l][n] = row[DTR + n];
        Cs[l][n] = row[DTR + NST + n];
    }
    __syncthreads();

    float aA[NST];
#pragma unroll
    for (int n = 0; n < NST; n++) aA[n] = -__expf(A_log[d * NST + n]);

    float s[NST];
#pragma unroll
    for (int n = 0; n < NST; n++) s[n] = 0.f;

    for (int l = 0; l < CHUNK; l++) {
        const size_t idx = (size_t)(b * LEN + base_l + l) * DIN + d;
        const float dl = delta[idx];
        const float uu = u[idx];
        const float du = dl * uu;
        float acc = 0.f;
#pragma unroll
        for (int n = 0; n < NST; n++) {
            const float dA = __expf(dl * aA[n]);
            s[n] = fmaf(dA, s[n], du * Bs[l][n]);
            acc  = fmaf(s[n], Cs[l][n], acc);
        }
        // gate: y * silu(res)
        const float r  = xr[(size_t)(b * LEN + base_l + l) * (2 * DIN) + DIN + d];
        const float sr = r / (1.f + __expf(-r));
        y[idx] = acc * sr;
    }
}

// ---------------- launcher ----------------
extern "C" void kernel_launch(void* const* d_in, const int* in_sizes, int n_in,
                              void* d_out, int out_size)
{
    const float* x      = (const float*)d_in[0];
    const float* W_in   = (const float*)d_in[1];
    const float* b_in   = (const float*)d_in[2];
    const float* conv_w = (const float*)d_in[3];
    const float* conv_b = (const float*)d_in[4];
    const float* W_x    = (const float*)d_in[5];
    const float* W_dt   = (const float*)d_in[6];
    const float* b_dt   = (const float*)d_in[7];
    const float* A_log  = (const float*)d_in[8];
    const float* W_out  = (const float*)d_in[9];
    const float* b_out  = (const float*)d_in[10];
    float* out = (float*)d_out;

    float *xr, *u, *xp, *dl, *y;
    cudaGetSymbolAddress((void**)&xr, g_xr);
    cudaGetSymbolAddress((void**)&u,  g_u);
    cudaGetSymbolAddress((void**)&xp, g_xp);
    cudaGetSymbolAddress((void**)&dl, g_dl);
    cudaGetSymbolAddress((void**)&y,  g_y);

    // 1) in_proj: xr[M,4096] = x[M,1024] @ W_in[4096,1024]^T + b_in
    sgemm_bt<0><<<dim3(2 * DIN / 128, MROWS / 128), 256>>>(
        x, W_in, b_in, xr, MROWS, 2 * DIN, DMODEL, DMODEL, DMODEL, 2 * DIN);

    // 2) depthwise causal conv + silu -> u
    conv_silu_kernel<<<(BSZ * LEN * DIN + 255) / 256, 256>>>(xr, conv_w, conv_b, u);

    // 3) x_proj: xp[M,96] = u[M,2048] @ W_x[96,2048]^T
    sgemm_bt<0><<<dim3(1, MROWS / 128), 256>>>(
        u, W_x, (const float*)nullptr, xp, MROWS, XPW, DIN, DIN, DIN, XPW);

    // 4) delta: softplus( dlt[M,64] @ W_dt[2048,64]^T + b_dt )   (dlt = xp[:, :64], lda = 96)
    sgemm_bt<1><<<dim3(DIN / 128, MROWS / 128), 256>>>(
        xp, W_dt, b_dt, dl, MROWS, DIN, DTR, XPW, DTR, DIN);

    // 5) chunked scan + gate -> y
    scan_kernel<<<dim3(DIN / 256, NC, BSZ), 256>>>(xp, dl, u, xr, A_log, y);

    // 6) out_proj: out[M,1024] = y[M,2048] @ W_out[1024,2048]^T + b_out
    sgemm_bt<0><<<dim3(DMODEL / 128, MROWS / 128), 256>>>(
        y, W_out, b_out, out, MROWS, DMODEL, DIN, DIN, DIN, DMODEL);
}

// round 8
// speedup vs baseline: 3.6856x; 3.6856x over previous
#include <cuda_runtime.h>
#include <cuda_bf16.h>
#include <cstdint>
#include <math.h>

// ---------------- problem constants ----------------
#define BSZ     2
#define LEN     1024
#define DMODEL  1024
#define DIN     2048      // d_inner
#define NST     16        // n_state
#define DTR     64        // dt_rank
#define XPW     96        // dt_rank + 2*n_state
#define CHUNK   256
#define NC      (LEN / CHUNK)
#define MROWS   (BSZ * LEN)   // 2048
#define XSPLIT  8             // split-K factor for x_proj

// ---------------- scratch (device globals; no allocation allowed) ----------------
__device__ __align__(16) float g_xr [(size_t)BSZ * LEN * 2 * DIN];      // in_proj output (xc | res)
__device__ __align__(16) float g_u  [(size_t)BSZ * LEN * DIN];          // conv+silu output
__device__ __align__(16) float g_xp [(size_t)BSZ * LEN * XPW];          // x_proj output (dlt|B|C)
__device__ __align__(16) float g_xpp[(size_t)XSPLIT * MROWS * XPW];     // x_proj split-K partials
__device__ __align__(16) float g_dl [(size_t)BSZ * LEN * DIN];          // delta (softplus'd)
__device__ __align__(16) float g_y  [(size_t)BSZ * LEN * DIN];          // gated scan output

// ======================= mma.sync helpers (sm_80+ PTX, works on plain sm_103) =======================
__device__ __forceinline__ uint32_t smem_u32(const void* p) {
    uint32_t a;
    asm("{ .reg .u64 t; cvta.to.shared.u64 t, %1; cvt.u32.u64 %0, t; }" : "=r"(a) : "l"(p));
    return a;
}

__device__ __forceinline__ void ldsm_x4(uint32_t r[4], uint32_t addr) {
    asm volatile("ldmatrix.sync.aligned.m8n8.x4.shared.b16 {%0,%1,%2,%3}, [%4];"
                 : "=r"(r[0]), "=r"(r[1]), "=r"(r[2]), "=r"(r[3]) : "r"(addr));
}

__device__ __forceinline__ void mma_bf16(float c[4], const uint32_t a[4],
                                         uint32_t b0, uint32_t b1) {
    asm volatile("mma.sync.aligned.m16n8k16.row.col.f32.bf16.bf16.f32 "
                 "{%0,%1,%2,%3}, {%4,%5,%6,%7}, {%8,%9}, {%0,%1,%2,%3};"
                 : "+f"(c[0]), "+f"(c[1]), "+f"(c[2]), "+f"(c[3])
                 : "r"(a[0]), "r"(a[1]), "r"(a[2]), "r"(a[3]), "r"(b0), "r"(b1));
}

__device__ __forceinline__ uint32_t pack2bf(float x0, float x1) {
    return (uint32_t)__bfloat16_as_ushort(__float2bfloat16_rn(x0)) |
           ((uint32_t)__bfloat16_as_ushort(__float2bfloat16_rn(x1)) << 16);
}

// decompose float4 -> bf16 hi (uint2 = 4 halves) and lo residual (uint2)
__device__ __forceinline__ void decomp4(float4 v, uint2& hi, uint2& lo) {
    float hx = __bfloat162float(__float2bfloat16_rn(v.x));
    float hy = __bfloat162float(__float2bfloat16_rn(v.y));
    float hz = __bfloat162float(__float2bfloat16_rn(v.z));
    float hw = __bfloat162float(__float2bfloat16_rn(v.w));
    hi = make_uint2(pack2bf(v.x, v.y), pack2bf(v.z, v.w));
    lo = make_uint2(pack2bf(v.x - hx, v.y - hy), pack2bf(v.z - hz, v.w - hw));
}

// ========== bf16x3 HMMA GEMM:  C[M,N] = A[M,K] @ B[N,K]^T (+bias)(+act) ==========
// Block tile 128x128, 256 threads = 8 warps (2x4), warp tile 64x32, K-chunk 32.
// A,B fp32 K-contiguous. Error-compensated: AhBh + AhBl + AlBh with fp32 accum.
// M % 128 == 0, K % 32 == 0; N guarded. Split-K via blockIdx.z (C slices of M*ldc).
// smem: 4 tiles of 128 rows x 40 halves (80B row stride -> conflict-free ldmatrix).
#define ROWH 40   // halves per smem row (32 data + 8 pad)
#define ROWB 80   // bytes per smem row

template <int ACT>   // 0 = none, 1 = softplus
__global__ void __launch_bounds__(256)
gemm_mma(const float* __restrict__ A, const float* __restrict__ B,
         const float* __restrict__ bias, float* __restrict__ C,
         int M, int N, int K, int lda, int ldb, int ldc)
{
    __shared__ __align__(16) __nv_bfloat16 sAh[128 * ROWH];
    __shared__ __align__(16) __nv_bfloat16 sAl[128 * ROWH];
    __shared__ __align__(16) __nv_bfloat16 sBh[128 * ROWH];
    __shared__ __align__(16) __nv_bfloat16 sBl[128 * ROWH];

    const int tid  = threadIdx.x;
    const int lane = tid & 31;
    const int wid  = tid >> 5;
    const int wm   = wid & 1;            // 2 warps along M
    const int wn   = wid >> 1;           // 4 warps along N
    const int brow = blockIdx.y * 128;
    const int bcol = blockIdx.x * 128;

    // split-K slice (no-op when gridDim.z == 1)
    const int koff = blockIdx.z * K;
    A += koff;
    B += koff;
    C += (size_t)blockIdx.z * M * ldc;

    // ---- gmem load mapping: each thread loads 4 float4 of A and 4 of B per chunk ----
    const int lrow = tid >> 3;           // 0..31
    const int lcol = tid & 7;            // float4 col 0..7 (32 floats per row-chunk)
    const uint32_t sts_off = (uint32_t)lrow * ROWB + lcol * 8;   // byte offset (row p adds 32*ROWB)

    const uint32_t uAh = smem_u32(sAh), uAl = smem_u32(sAl);
    const uint32_t uBh = smem_u32(sBh), uBl = smem_u32(sBl);

    // ---- ldmatrix per-lane base addresses ----
    // A frag (m16k16, x4): lanes 0-15 rows 0-15 @ col 0; lanes 16-31 rows 0-15 @ col 8
    const uint32_t a_lbase = (uint32_t)(wm * 64 + (lane & 15)) * ROWB + ((lane >> 4) << 3) * 2;
    // B frag (two n8k16 tiles per x4): row = np*16 + ((l>>4)<<3) + (l&7); col = ((l>>3)&1)*8
    const uint32_t b_lbase = (uint32_t)(wn * 32 + (((lane >> 4) & 1) << 3) + (lane & 7)) * ROWB
                           + (((lane >> 3) & 1) << 3) * 2;

    float c[4][4][4];
#pragma unroll
    for (int mi = 0; mi < 4; mi++)
#pragma unroll
        for (int ni = 0; ni < 4; ni++)
#pragma unroll
            for (int r = 0; r < 4; r++) c[mi][ni][r] = 0.f;

    const int nchunks = K >> 5;

    // ---- prefetch chunk 0 ----
    float4 pa[4], pb[4];
#pragma unroll
    for (int p = 0; p < 4; p++) {
        const int row = lrow + p * 32;
        pa[p] = *(const float4*)(A + (size_t)(brow + row) * lda + lcol * 4);
        float4 bv = make_float4(0.f, 0.f, 0.f, 0.f);
        if (bcol + row < N) bv = *(const float4*)(B + (size_t)(bcol + row) * ldb + lcol * 4);
        pb[p] = bv;
    }

    for (int ck = 0; ck < nchunks; ck++) {
        // ---- convert + store current chunk to smem ----
        __syncthreads();   // previous chunk's fragments fully consumed
#pragma unroll
        for (int p = 0; p < 4; p++) {
            const uint32_t off = sts_off + p * 32 * ROWB;
            uint2 hi, lo;
            decomp4(pa[p], hi, lo);
            *(uint2*)((char*)sAh + off) = hi;
            *(uint2*)((char*)sAl + off) = lo;
            decomp4(pb[p], hi, lo);
            *(uint2*)((char*)sBh + off) = hi;
            *(uint2*)((char*)sBl + off) = lo;
        }
        __syncthreads();

        // ---- prefetch next chunk ----
        if (ck + 1 < nchunks) {
            const int k0 = (ck + 1) * 32;
#pragma unroll
            for (int p = 0; p < 4; p++) {
                const int row = lrow + p * 32;
                pa[p] = *(const float4*)(A + (size_t)(brow + row) * lda + k0 + lcol * 4);
                float4 bv = make_float4(0.f, 0.f, 0.f, 0.f);
                if (bcol + row < N) bv = *(const float4*)(B + (size_t)(bcol + row) * ldb + k0 + lcol * 4);
                pb[p] = bv;
            }
        }

        // ---- compute: 2 k16 steps ----
#pragma unroll
        for (int ks = 0; ks < 2; ks++) {
            const uint32_t kso = ks * 32;   // 16 halves = 32 bytes
            uint32_t ah[4][4], al[4][4], bh[2][4], bl[2][4];
#pragma unroll
            for (int mi = 0; mi < 4; mi++) {
                const uint32_t o = a_lbase + mi * (16 * ROWB) + kso;
                ldsm_x4(ah[mi], uAh + o);
                ldsm_x4(al[mi], uAl + o);
            }
#pragma unroll
            for (int np = 0; np < 2; np++) {
                const uint32_t o = b_lbase + np * (16 * ROWB) + kso;
                ldsm_x4(bh[np], uBh + o);
                ldsm_x4(bl[np], uBl + o);
            }
#pragma unroll
            for (int mi = 0; mi < 4; mi++)
#pragma unroll
                for (int np = 0; np < 2; np++)
#pragma unroll
                    for (int s = 0; s < 2; s++) {
                        const int ni = np * 2 + s;
                        mma_bf16(c[mi][ni], ah[mi], bh[np][s * 2], bh[np][s * 2 + 1]);
                        mma_bf16(c[mi][ni], ah[mi], bl[np][s * 2], bl[np][s * 2 + 1]);
                        mma_bf16(c[mi][ni], al[mi], bh[np][s * 2], bh[np][s * 2 + 1]);
                    }
        }
    }

    // ---- epilogue ----
#pragma unroll
    for (int mi = 0; mi < 4; mi++) {
        const int r0 = brow + wm * 64 + mi * 16 + (lane >> 2);
#pragma unroll
        for (int ni = 0; ni < 4; ni++) {
            const int col = bcol + wn * 32 + ni * 8 + (lane & 3) * 2;
#pragma unroll
            for (int half = 0; half < 2; half++) {
                const int row = r0 + half * 8;
                float v0 = c[mi][ni][half * 2 + 0];
                float v1 = c[mi][ni][half * 2 + 1];
                if (col < N) {
                    if (bias) v0 += bias[col];
                    if (ACT == 1) v0 = (v0 > 20.f) ? v0 : log1pf(__expf(v0));
                    C[(size_t)row * ldc + col] = v0;
                }
                if (col + 1 < N) {
                    if (bias) v1 += bias[col + 1];
                    if (ACT == 1) v1 = (v1 > 20.f) ? v1 : log1pf(__expf(v1));
                    C[(size_t)row * ldc + col + 1] = v1;
                }
            }
        }
    }
}

// ---------------- split-K reduce for x_proj ----------------
__global__ void reduce_xp_kernel(const float* __restrict__ part, float* __restrict__ xp)
{
    const int i = blockIdx.x * 256 + threadIdx.x;
    if (i >= MROWS * XPW) return;
    float s = 0.f;
#pragma unroll
    for (int k = 0; k < XSPLIT; k++) s += part[(size_t)k * MROWS * XPW + i];
    xp[i] = s;
}

// ---------------- depthwise causal conv1d (k=3) + SiLU ----------------
__global__ void conv_silu_kernel(const float* __restrict__ xr,
                                 const float* __restrict__ conv_w,
                                 const float* __restrict__ conv_b,
                                 float* __restrict__ u)
{
    const int idx = blockIdx.x * blockDim.x + threadIdx.x;   // over B*L*D
    if (idx >= BSZ * LEN * DIN) return;
    const int d = idx % DIN;
    const int l = (idx / DIN) % LEN;
    const int b = idx / (DIN * LEN);

    const float* xc = xr + (size_t)b * LEN * (2 * DIN);
    const float w0 = conv_w[d * 3 + 0];
    const float w1 = conv_w[d * 3 + 1];
    const float w2 = conv_w[d * 3 + 2];

    float acc = conv_b[d];
    if (l >= 2) acc = fmaf(w0, xc[(size_t)(l - 2) * (2 * DIN) + d], acc);
    if (l >= 1) acc = fmaf(w1, xc[(size_t)(l - 1) * (2 * DIN) + d], acc);
    acc = fmaf(w2, xc[(size_t)l * (2 * DIN) + d], acc);
    u[idx] = acc / (1.f + __expf(-acc));
}

// ---------------- chunked selective scan + output gate ----------------
__global__ void __launch_bounds__(256)
scan_kernel(const float* __restrict__ xp, const float* __restrict__ delta,
            const float* __restrict__ u, const float* __restrict__ xr,
            const float* __restrict__ A_log, float* __restrict__ y)
{
    const int d = blockIdx.x * 256 + threadIdx.x;
    const int c = blockIdx.y;
    const int b = blockIdx.z;
    const int base_l = c * CHUNK;

    __shared__ float Bs[CHUNK][NST];
    __shared__ float Cs[CHUNK][NST];
    for (int i = threadIdx.x; i < CHUNK * NST; i += 256) {
        const int l = i / NST, n = i % NST;
        const float* row = xp + (size_t)(b * LEN + base_l + l) * XPW;
        Bs[l][n] = row[DTR + n];
        Cs[l][n] = row[DTR + NST + n];
    }
    __syncthreads();

    float aA[NST];
#pragma unroll
    for (int n = 0; n < NST; n++) aA[n] = -__expf(A_log[d * NST + n]);

    float s[NST];
#pragma unroll
    for (int n = 0; n < NST; n++) s[n] = 0.f;

    for (int l = 0; l < CHUNK; l++) {
        const size_t idx = (size_t)(b * LEN + base_l + l) * DIN + d;
        const float dl = delta[idx];
        const float uu = u[idx];
        const float du = dl * uu;
        float acc = 0.f;
#pragma unroll
        for (int n = 0; n < NST; n++) {
            const float dA = __expf(dl * aA[n]);
            s[n] = fmaf(dA, s[n], du * Bs[l][n]);
            acc  = fmaf(s[n], Cs[l][n], acc);
        }
        const float r  = xr[(size_t)(b * LEN + base_l + l) * (2 * DIN) + DIN + d];
        const float sr = r / (1.f + __expf(-r));
        y[idx] = acc * sr;
    }
}

// ---------------- launcher ----------------
extern "C" void kernel_launch(void* const* d_in, const int* in_sizes, int n_in,
                              void* d_out, int out_size)
{
    const float* x      = (const float*)d_in[0];
    const float* W_in   = (const float*)d_in[1];
    const float* b_in   = (const float*)d_in[2];
    const float* conv_w = (const float*)d_in[3];
    const float* conv_b = (const float*)d_in[4];
    const float* W_x    = (const float*)d_in[5];
    const float* W_dt   = (const float*)d_in[6];
    const float* b_dt   = (const float*)d_in[7];
    const float* A_log  = (const float*)d_in[8];
    const float* W_out  = (const float*)d_in[9];
    const float* b_out  = (const float*)d_in[10];
    float* out = (float*)d_out;

    float *xr, *u, *xp, *xpp, *dl, *y;
    cudaGetSymbolAddress((void**)&xr,  g_xr);
    cudaGetSymbolAddress((void**)&u,   g_u);
    cudaGetSymbolAddress((void**)&xp,  g_xp);
    cudaGetSymbolAddress((void**)&xpp, g_xpp);
    cudaGetSymbolAddress((void**)&dl,  g_dl);
    cudaGetSymbolAddress((void**)&y,   g_y);

    // 1) in_proj: xr[2048,4096] = x[2048,1024] @ W_in[4096,1024]^T + b_in
    gemm_mma<0><<<dim3(2 * DIN / 128, MROWS / 128, 1), 256>>>(
        x, W_in, b_in, xr, MROWS, 2 * DIN, DMODEL, DMODEL, DMODEL, 2 * DIN);

    // 2) depthwise causal conv + silu -> u
    conv_silu_kernel<<<(BSZ * LEN * DIN + 255) / 256, 256>>>(xr, conv_w, conv_b, u);

    // 3) x_proj split-K partials: xpp[8][2048][96] = u-slices @ W_x-slices^T
    gemm_mma<0><<<dim3(1, MROWS / 128, XSPLIT), 256>>>(
        u, W_x, (const float*)nullptr, xpp, MROWS, XPW, DIN / XSPLIT, DIN, DIN, XPW);

    // 3b) reduce partials -> xp
    reduce_xp_kernel<<<(MROWS * XPW + 255) / 256, 256>>>(xpp, xp);

    // 4) delta = softplus( xp[:, :64] @ W_dt[2048,64]^T + b_dt )   (lda = 96)
    gemm_mma<1><<<dim3(DIN / 128, MROWS / 128, 1), 256>>>(
        xp, W_dt, b_dt, dl, MROWS, DIN, DTR, XPW, DTR, DIN);

    // 5) chunked scan + gate -> y
    scan_kernel<<<dim3(DIN / 256, NC, BSZ), 256>>>(xp, dl, u, xr, A_log, y);

    // 6) out_proj: out[2048,1024] = y[2048,2048] @ W_out[1024,2048]^T + b_out
    gemm_mma<0><<<dim3(DMODEL / 128, MROWS / 128, 1), 256>>>(
        y, W_out, b_out, out, MROWS, DMODEL, DIN, DIN, DIN, DMODEL);
}